// round 17
// baseline (speedup 1.0000x reference)
#include <cuda_runtime.h>
#include <cuda_fp16.h>
#include <cstdint>

#define C 32
#define H 128
#define W 256
#define MW 128       // columns per block (w-split x2)
#define XS 20        // x_sh row stride in u32 (80B): frag bank 20g+t4 -> conflict-free
#define YSY 20
#define YR 200       // y rows: jj = w0-64+r, r in [0,200)
#define GO 66
#define GS 67        // gather: lane w-stride 1 -> bank stride 3 -> conflict-free
#define NT 256

// pack two f32 -> half2 {lo=v0, hi=v1}
__device__ __forceinline__ uint32_t f2h2(float v0, float v1) {
    uint32_t r;
    asm("cvt.rn.f16x2.f32 %0, %1, %2;" : "=r"(r) : "f"(v1), "f"(v0));
    return r;
}

__global__ __launch_bounds__(NT, 3)
void cost_volume_kernel(const float* __restrict__ x, const float* __restrict__ y,
                        const float* __restrict__ disp, float* __restrict__ out,
                        int D) {
    extern __shared__ uint32_t smu[];
    uint32_t* x_sh = smu;                         // [MW][XS]  halves [w][c]
    uint32_t* y_sh = smu + MW * XS;               // [YR][YSY] halves [r][c], r = jj-(w0-64)
    float* G_sh = (float*)(smu + MW * XS + YR * YSY);  // [MW][GS] fp32 band

    const int blk = blockIdx.x;
    const int s = blk & 1;
    const int bh = blk >> 1;
    const int b = bh / H;
    const int h = bh - b * H;
    const int w0 = s << 7;               // 0 or 128
    const int tid = threadIdx.x;
    const size_t HW = (size_t)H * W;
    const float* ybase = y + ((size_t)b * C * H + h) * W;
    const float* xbase = x + ((size_t)b * C * H + h) * W;

    // ---- Phase 1: stage x cols [w0, w0+128) and y cols [w0-64, w0+136) as
    // fp16 pairs; out-of-range y rows zeroed (reference's zero-padding mask).
    {   // x: 2 threads per column (k halves)
        const int col = tid & 127;
        const int kh = (tid >> 7) << 3;          // 0 or 8
        const float* src = xbase + w0 + col;
        uint32_t* dst = x_sh + col * XS + kh;
        #pragma unroll
        for (int k = 0; k < 8; k++)
            dst[k] = f2h2(src[(size_t)(2 * (kh + k)) * HW],
                          src[(size_t)(2 * (kh + k) + 1) * HW]);
    }
    if (tid < YR) {                              // y: one thread per row
        const int jj = w0 - 64 + tid;
        uint32_t* dst = y_sh + tid * YSY;
        if ((unsigned)jj < (unsigned)W) {
            const float* src = ybase + jj;
            #pragma unroll
            for (int k = 0; k < 16; k++)
                dst[k] = f2h2(src[(size_t)(2 * k) * HW], src[(size_t)(2 * k + 1) * HW]);
        } else {
            #pragma unroll
            for (int k = 0; k < 16; k++) dst[k] = 0u;
        }
    }

    // Phase-3 disp prefetch (strided-w scheme), issued before the barrier.
    const float* dbase = disp + ((size_t)b * D * H + h) * W + w0;
    float* obase = out + ((size_t)b * D * H + h) * W + w0;
    const int q = tid & 63;
    const int d0 = (tid >> 6) * 12;              // D==48 fast path: 4 groups x 12
    float dv[12];
    const bool fast = (D == 48);
    if (fast) {
        #pragma unroll
        for (int j = 0; j < 12; j++)
            dv[j] = dbase[(size_t)(d0 + j) * HW + q];
    }
    __syncthreads();

    // ---- Phase 2: banded Gram via mma.sync m16n8k16 (f16 x f16 -> f32).
    // Each warp owns one 16-row M-tile; 11 N-tiles cover the tile's whole
    // band [wt0-64, wt0+24) -> full coverage, no cleanup.
    {
        const int lane = tid & 31;
        const int g = lane >> 2;
        const int t4 = lane & 3;
        const int wt0 = (tid >> 5) << 4;          // local M-tile base (8 warps)
        const uint32_t* xr0 = x_sh + (wt0 + g) * XS;
        const uint32_t* xr8 = x_sh + (wt0 + g + 8) * XS;
        uint32_t a00 = xr0[t4],      a01 = xr8[t4];
        uint32_t a02 = xr0[t4 + 4],  a03 = xr8[t4 + 4];
        uint32_t a10 = xr0[t4 + 8],  a11 = xr8[t4 + 8];
        uint32_t a12 = xr0[t4 + 12], a13 = xr8[t4 + 12];
        float* grow  = G_sh + (wt0 + g) * GS;
        float* grow8 = G_sh + (wt0 + g + 8) * GS;
        #pragma unroll
        for (int nt = 0; nt < 11; nt++) {
            const uint32_t* yr = y_sh + (wt0 + nt * 8 + g) * YSY;  // local row
            uint32_t b00 = yr[t4];
            uint32_t b01 = yr[t4 + 4];
            uint32_t b10 = yr[t4 + 8];
            uint32_t b11 = yr[t4 + 12];
            float c0 = 0.f, c1 = 0.f, c2 = 0.f, c3 = 0.f;
            asm volatile(
                "mma.sync.aligned.m16n8k16.row.col.f32.f16.f16.f32 "
                "{%0,%1,%2,%3}, {%4,%5,%6,%7}, {%8,%9}, {%0,%1,%2,%3};"
                : "+f"(c0), "+f"(c1), "+f"(c2), "+f"(c3)
                : "r"(a00), "r"(a01), "r"(a02), "r"(a03), "r"(b00), "r"(b01));
            asm volatile(
                "mma.sync.aligned.m16n8k16.row.col.f32.f16.f16.f32 "
                "{%0,%1,%2,%3}, {%4,%5,%6,%7}, {%8,%9}, {%0,%1,%2,%3};"
                : "+f"(c0), "+f"(c1), "+f"(c2), "+f"(c3)
                : "r"(a10), "r"(a11), "r"(a12), "r"(a13), "r"(b10), "r"(b11));
            // o = 8*nt + col - row (rows g / g+8; cols 2t4, 2t4+1)
            int o0 = nt * 8 + 2 * t4 - g;
            if ((unsigned)o0 <= 65u) grow[o0] = c0;
            if ((unsigned)(o0 + 1) <= 65u) grow[o0 + 1] = c1;
            int o8 = o0 - 8;
            if ((unsigned)o8 <= 65u) grow8[o8] = c2;
            if ((unsigned)(o8 + 1) <= 65u) grow8[o8 + 1] = c3;
        }
    }
    __syncthreads();

    // ---- Phase 3: strided-w gather. Thread (q, g3) owns local w in
    // {q, q+64}, d in [12*g3, 12*g3+12). Lanes consecutive w -> conflict-free
    // gather LDS + coalesced LDG/STG. disp in [0,64) => o in [0,64] -> no guards.
    if (fast) {
        #pragma unroll
        for (int sl = 0; sl < 2; sl++) {
            const int w3 = q + sl * 64;           // local col
            float dnx[12];
            if (sl == 0) {
                #pragma unroll
                for (int j = 0; j < 12; j++)
                    dnx[j] = dbase[(size_t)(d0 + j) * HW + w3 + 64];
            }
            const float* gr = G_sh + w3 * GS;
            const float wf = (float)(w0 + w3);
            #pragma unroll
            for (int j = 0; j < 12; j++) {
                float px = wf - dv[j];
                float x0f = floorf(px);
                float fx = px - x0f;
                int o = (int)x0f - (w0 + w3) + 64;
                float g0 = gr[o];
                float g1 = gr[o + 1];
                obase[(size_t)(d0 + j) * HW + w3] = (g0 + (g1 - g0) * fx) * (1.0f / C);
            }
            if (sl == 0) {
                #pragma unroll
                for (int j = 0; j < 12; j++) dv[j] = dnx[j];
            }
        }
    } else {
        const int total4 = D * (MW / 4);
        #pragma unroll 4
        for (int i = tid; i < total4; i += NT) {
            int d = i >> 5;                       // 32 float4 per d
            int w4 = (i & 31) << 2;
            float4 dvv = *(const float4*)(dbase + (size_t)d * HW + w4);
            float4 res;
            #pragma unroll
            for (int j = 0; j < 4; j++) {
                int wwl = w4 + j;
                int wwg = w0 + wwl;
                float px = (float)wwg - (&dvv.x)[j];
                float x0f = floorf(px);
                float fx = px - x0f;
                int o = (int)x0f - wwg + 64;
                float g0 = ((unsigned)o < GO) ? G_sh[wwl * GS + o] : 0.f;
                float g1 = ((unsigned)(o + 1) < GO) ? G_sh[wwl * GS + o + 1] : 0.f;
                (&res.x)[j] = (g0 + (g1 - g0) * fx) * (1.0f / C);
            }
            *(float4*)(obase + (size_t)d * HW + w4) = res;
        }
    }
}

extern "C" void kernel_launch(void* const* d_in, const int* in_sizes, int n_in,
                              void* d_out, int out_size) {
    const float* x = (const float*)d_in[0];
    const float* y = (const float*)d_in[1];
    const float* disp = (const float*)d_in[2];
    int B = in_sizes[0] / (C * H * W);
    int D = in_sizes[2] / (B * H * W);
    int smem = (MW * XS + YR * YSY + MW * GS) * 4;
    cudaFuncSetAttribute(cost_volume_kernel,
                         cudaFuncAttributeMaxDynamicSharedMemorySize, smem);
    cost_volume_kernel<<<B * H * 2, NT, smem>>>(x, y, disp, (float*)d_out, D);
}